// round 3
// baseline (speedup 1.0000x reference)
#include <cuda_runtime.h>
#include <cuda_fp16.h>
#include <cstdint>

// ---------------- problem dims ----------------
#define MDIM 8192
#define NDIM 4096
#define KDIM 4096

// ---------------- GEMM tiling ----------------
#define BM 256
#define BN 256
#define BK 64                  // 64 fp16 = 128 B per SMEM row
#define STAGES 3
#define KT_ITERS (KDIM / BK)   // 64
#define THREADS 512            // 16 warps: 4 (m) x 4 (n), warp tile 64x64

// SMEM per stage: A 256*128B = 32KB, B 256*128B = 32KB
#define OFF_A 0
#define OFF_B 32768
#define STAGE_BYTES 65536
#define SMEM_TOTAL (STAGES * STAGE_BYTES)   // 196608

// ---------------- scratch (allocation-free __device__ globals) ----------------
__device__ __half g_A [(size_t)MDIM * KDIM];   // 64 MB fp16 activations
__device__ __half g_Bw[(size_t)NDIM * KDIM];   // 32 MB fp16 unpacked weights

// ---------------- PTX helpers ----------------
__device__ __forceinline__ uint32_t smem_u32(const void* p) {
    return (uint32_t)__cvta_generic_to_shared(p);
}
__device__ __forceinline__ void cp16(uint32_t s, const void* g) {
    asm volatile("cp.async.cg.shared.global [%0], [%1], 16;" :: "r"(s), "l"(g));
}
__device__ __forceinline__ void cp_commit() {
    asm volatile("cp.async.commit_group;" ::: "memory");
}
template <int N>
__device__ __forceinline__ void cp_wait() {
    asm volatile("cp.async.wait_group %0;" :: "n"(N) : "memory");
}
__device__ __forceinline__ void ldsm_x4(uint32_t* d, uint32_t addr) {
    asm volatile("ldmatrix.sync.aligned.m8n8.x4.shared.b16 {%0,%1,%2,%3}, [%4];"
                 : "=r"(d[0]), "=r"(d[1]), "=r"(d[2]), "=r"(d[3]) : "r"(addr));
}
__device__ __forceinline__ void mma16816(float* c, const uint32_t* a,
                                         uint32_t b0, uint32_t b1) {
    asm volatile(
        "mma.sync.aligned.m16n8k16.row.col.f32.f16.f16.f32 "
        "{%0,%1,%2,%3}, {%4,%5,%6,%7}, {%8,%9}, {%0,%1,%2,%3};"
        : "+f"(c[0]), "+f"(c[1]), "+f"(c[2]), "+f"(c[3])
        : "r"(a[0]), "r"(a[1]), "r"(a[2]), "r"(a[3]), "r"(b0), "r"(b1));
}

// ---------------- kernel 1: unpack int4 -> exact fp16 ----------------
// wp[i] holds one byte: low nibble -> even k, high nibble -> odd k.
// XOR 0x88 + sign-extend collapses to (nibble - 8), exact in fp16.
__global__ __launch_bounds__(256) void unpack_w_kernel(const int* __restrict__ wp) {
    int idx = blockIdx.x * 256 + threadIdx.x;     // 0 .. N*K/2-1
    int v = wp[idx];
    float lo = (float)((v & 0xF) - 8);
    float hi = (float)(((v >> 4) & 0xF) - 8);
    reinterpret_cast<__half2*>(g_Bw)[idx] = __floats2half2_rn(lo, hi);
}

// ---------------- kernel 2: x f32 -> fp16 ----------------
__global__ __launch_bounds__(256) void cvt_x_kernel(const float4* __restrict__ x4) {
    int idx = blockIdx.x * 256 + threadIdx.x;     // 0 .. M*K/4-1
    float4 v = x4[idx];
    __half2 h0 = __floats2half2_rn(v.x, v.y);
    __half2 h1 = __floats2half2_rn(v.z, v.w);
    __half2* H = reinterpret_cast<__half2*>(g_A);
    H[2 * idx]     = h0;
    H[2 * idx + 1] = h1;
}

// ---------------- stage loader: A 2048 chunks + B 2048 chunks of 16B ----------------
__device__ __forceinline__ void load_stage(uint32_t sbase, int tid, int kt,
                                           int m0, int n0) {
    const char* ga = (const char*)(g_A  + (size_t)m0 * KDIM + kt * BK);
    const char* gb = (const char*)(g_Bw + (size_t)n0 * KDIM + kt * BK);
    #pragma unroll
    for (int j = 0; j < 4; j++) {          // A: 256 rows x 8 units
        int c = tid + j * THREADS;
        int row = c >> 3, u = c & 7;
        uint32_t sa = sbase + OFF_A + row * 128 + (((uint32_t)(u ^ (row & 7))) << 4);
        cp16(sa, ga + (size_t)row * (KDIM * 2) + u * 16);
    }
    #pragma unroll
    for (int j = 0; j < 4; j++) {          // B: 256 rows x 8 units
        int c = tid + j * THREADS;
        int row = c >> 3, u = c & 7;
        uint32_t sa = sbase + OFF_B + row * 128 + (((uint32_t)(u ^ (row & 7))) << 4);
        cp16(sa, gb + (size_t)row * (KDIM * 2) + u * 16);
    }
}

// ---------------- kernel 3: fp16 mma.sync GEMM + fused epilogue ----------------
__global__ __launch_bounds__(THREADS, 1) void gemm_kernel(
    const float* __restrict__ scales, const float* __restrict__ bias,
    float* __restrict__ out)
{
    extern __shared__ char smem[];
    const uint32_t sb = smem_u32(smem);
    const int tid = threadIdx.x;
    const int wid = tid >> 5;
    const int lane = tid & 31;

    const int tn = blockIdx.x & 15;   // 16 N-tiles (fastest -> A reuse in L2)
    const int tm = blockIdx.x >> 4;   // 32 M-tiles
    const int m0 = tm * BM;
    const int n0 = tn * BN;

    const int warp_m = wid & 3;       // 4 groups of 64 rows
    const int warp_n = wid >> 2;      // 4 groups of 64 cols

    // per-lane ldmatrix addressing (swizzled: unit16 u ^ (row & 7))
    const int a_row = warp_m * 64 + (lane & 15);
    const int a_u0  = lane >> 4;                         // + 2*ks
    const int b_row = warp_n * 64 + (lane & 7) + ((lane >> 4) << 3);
    const int b_u0  = (lane >> 3) & 1;                   // + 2*ks

    float c[4][8][4];
    #pragma unroll
    for (int i = 0; i < 4; i++)
        #pragma unroll
        for (int j = 0; j < 8; j++)
            #pragma unroll
            for (int r = 0; r < 4; r++) c[i][j][r] = 0.0f;

    // prologue: fill STAGES-1 stages
    #pragma unroll
    for (int p = 0; p < STAGES - 1; p++) {
        load_stage(sb + p * STAGE_BYTES, tid, p, m0, n0);
        cp_commit();
    }

    #pragma unroll 1
    for (int kt = 0; kt < KT_ITERS; kt++) {
        cp_wait<STAGES - 2>();
        __syncthreads();

        int pk = kt + STAGES - 1;
        if (pk < KT_ITERS)
            load_stage(sb + (pk % STAGES) * STAGE_BYTES, tid, pk, m0, n0);
        cp_commit();

        const uint32_t sA  = sb + (kt % STAGES) * STAGE_BYTES + OFF_A;
        const uint32_t sBm = sb + (kt % STAGES) * STAGE_BYTES + OFF_B;

        #pragma unroll
        for (int ks = 0; ks < 4; ks++) {
            uint32_t a[4][4], b[4][4];
            #pragma unroll
            for (int i = 0; i < 4; i++) {
                int r = a_row + i * 16;
                uint32_t addr = sA + r * 128 +
                                (((uint32_t)((a_u0 + 2 * ks) ^ (r & 7))) << 4);
                ldsm_x4(a[i], addr);
            }
            #pragma unroll
            for (int j = 0; j < 4; j++) {
                int r = b_row + j * 16;
                uint32_t addr = sBm + r * 128 +
                                (((uint32_t)((b_u0 + 2 * ks) ^ (r & 7))) << 4);
                ldsm_x4(b[j], addr);
            }
            #pragma unroll
            for (int i = 0; i < 4; i++) {
                #pragma unroll
                for (int j = 0; j < 4; j++) {
                    mma16816(c[i][2 * j],     a[i], b[j][0], b[j][1]);
                    mma16816(c[i][2 * j + 1], a[i], b[j][2], b[j][3]);
                }
            }
        }
    }
    cp_wait<0>();

    // ---------------- epilogue: scale * acc + bias ----------------
    const int mrow = lane >> 2;
    const int ncol = (lane & 3) * 2;
    #pragma unroll
    for (int j = 0; j < 8; j++) {
        int n = n0 + warp_n * 64 + j * 8 + ncol;
        float2 s  = *reinterpret_cast<const float2*>(scales + n);
        float2 bb = *reinterpret_cast<const float2*>(bias + n);
        #pragma unroll
        for (int i = 0; i < 4; i++) {
            int m = m0 + warp_m * 64 + i * 16 + mrow;
            float2 v0, v1;
            v0.x = c[i][j][0] * s.x + bb.x;
            v0.y = c[i][j][1] * s.y + bb.y;
            v1.x = c[i][j][2] * s.x + bb.x;
            v1.y = c[i][j][3] * s.y + bb.y;
            *reinterpret_cast<float2*>(out + (size_t)m * NDIM + n) = v0;
            *reinterpret_cast<float2*>(out + (size_t)(m + 8) * NDIM + n) = v1;
        }
    }
}

// ---------------- launch ----------------
extern "C" void kernel_launch(void* const* d_in, const int* in_sizes, int n_in,
                              void* d_out, int out_size) {
    const float* x  = (const float*)d_in[0];
    const int*   wp = (const int*)d_in[1];
    const float* sc = (const float*)d_in[2];
    const float* bi = (const float*)d_in[3];
    float* out = (float*)d_out;

    static bool attr_set = false;
    if (!attr_set) {
        cudaFuncSetAttribute(gemm_kernel,
                             cudaFuncAttributeMaxDynamicSharedMemorySize, SMEM_TOTAL);
        attr_set = true;
    }

    unpack_w_kernel<<<(NDIM * (KDIM / 2)) / 256, 256>>>(wp);            // 32768 blocks
    cvt_x_kernel<<<(MDIM * (KDIM / 4)) / 256, 256>>>((const float4*)x); // 32768 blocks
    gemm_kernel<<<(MDIM / BM) * (NDIM / BN), THREADS, SMEM_TOTAL>>>(sc, bi, out);
}

// round 4
// speedup vs baseline: 3.4881x; 3.4881x over previous
#include <cuda_runtime.h>
#include <cuda_fp16.h>
#include <cstdint>

// ---------------- problem dims ----------------
#define MDIM 8192
#define NDIM 4096
#define KDIM 4096

// ---------------- GEMM tiling ----------------
#define BM 128
#define BN 256
#define BK 64                  // 64 fp16 = 128 B per SMEM row
#define STAGES 4
#define KT_ITERS (KDIM / BK)   // 64
#define THREADS 256            // 8 warps: 2 (m) x 4 (n), warp tile 64x64
                               // 256 threads -> up to 255 regs/thread (no spill)

// SMEM per stage: A 128*128B = 16KB, B 256*128B = 32KB
#define OFF_A 0
#define OFF_B 16384
#define STAGE_BYTES 49152
#define SMEM_TOTAL (STAGES * STAGE_BYTES)   // 196608

// ---------------- scratch (allocation-free __device__ globals) ----------------
__device__ __half g_A [(size_t)MDIM * KDIM];   // 64 MB fp16 activations
__device__ __half g_Bw[(size_t)NDIM * KDIM];   // 32 MB fp16 unpacked weights

// ---------------- PTX helpers ----------------
__device__ __forceinline__ uint32_t smem_u32(const void* p) {
    return (uint32_t)__cvta_generic_to_shared(p);
}
__device__ __forceinline__ void cp16(uint32_t s, const void* g) {
    asm volatile("cp.async.cg.shared.global [%0], [%1], 16;" :: "r"(s), "l"(g));
}
__device__ __forceinline__ void cp_commit() {
    asm volatile("cp.async.commit_group;" ::: "memory");
}
template <int N>
__device__ __forceinline__ void cp_wait() {
    asm volatile("cp.async.wait_group %0;" :: "n"(N) : "memory");
}
__device__ __forceinline__ void ldsm_x4(uint32_t* d, uint32_t addr) {
    asm volatile("ldmatrix.sync.aligned.m8n8.x4.shared.b16 {%0,%1,%2,%3}, [%4];"
                 : "=r"(d[0]), "=r"(d[1]), "=r"(d[2]), "=r"(d[3]) : "r"(addr));
}
__device__ __forceinline__ void mma16816(float* c, const uint32_t* a,
                                         uint32_t b0, uint32_t b1) {
    asm volatile(
        "mma.sync.aligned.m16n8k16.row.col.f32.f16.f16.f32 "
        "{%0,%1,%2,%3}, {%4,%5,%6,%7}, {%8,%9}, {%0,%1,%2,%3};"
        : "+f"(c[0]), "+f"(c[1]), "+f"(c[2]), "+f"(c[3])
        : "r"(a[0]), "r"(a[1]), "r"(a[2]), "r"(a[3]), "r"(b0), "r"(b1));
}

// ---------------- kernel 1: unpack int4 -> exact fp16 ----------------
// wp[i] holds one byte: low nibble -> even k, high nibble -> odd k.
// XOR 0x88 + sign-extend collapses to (nibble - 8), exact in fp16.
__global__ __launch_bounds__(256) void unpack_w_kernel(const int* __restrict__ wp) {
    int idx = blockIdx.x * 256 + threadIdx.x;     // 0 .. N*K/2-1
    int v = wp[idx];
    float lo = (float)((v & 0xF) - 8);
    float hi = (float)(((v >> 4) & 0xF) - 8);
    reinterpret_cast<__half2*>(g_Bw)[idx] = __floats2half2_rn(lo, hi);
}

// ---------------- kernel 2: x f32 -> fp16 ----------------
__global__ __launch_bounds__(256) void cvt_x_kernel(const float4* __restrict__ x4) {
    int idx = blockIdx.x * 256 + threadIdx.x;     // 0 .. M*K/4-1
    float4 v = x4[idx];
    __half2 h0 = __floats2half2_rn(v.x, v.y);
    __half2 h1 = __floats2half2_rn(v.z, v.w);
    __half2* H = reinterpret_cast<__half2*>(g_A);
    H[2 * idx]     = h0;
    H[2 * idx + 1] = h1;
}

// ---------------- stage loader: A 1024 + B 2048 chunks of 16B ----------------
__device__ __forceinline__ void load_stage(uint32_t sbase, int tid, int kt,
                                           int m0, int n0) {
    const char* ga = (const char*)(g_A  + (size_t)m0 * KDIM + kt * BK);
    const char* gb = (const char*)(g_Bw + (size_t)n0 * KDIM + kt * BK);
    #pragma unroll
    for (int j = 0; j < 4; j++) {          // A: 128 rows x 8 units
        int c = tid + j * THREADS;
        int row = c >> 3, u = c & 7;
        uint32_t sa = sbase + OFF_A + row * 128 + (((uint32_t)(u ^ (row & 7))) << 4);
        cp16(sa, ga + (size_t)row * (KDIM * 2) + u * 16);
    }
    #pragma unroll
    for (int j = 0; j < 8; j++) {          // B: 256 rows x 8 units
        int c = tid + j * THREADS;
        int row = c >> 3, u = c & 7;
        uint32_t sa = sbase + OFF_B + row * 128 + (((uint32_t)(u ^ (row & 7))) << 4);
        cp16(sa, gb + (size_t)row * (KDIM * 2) + u * 16);
    }
}

// ---------------- kernel 3: fp16 mma.sync GEMM + fused epilogue ----------------
__global__ __launch_bounds__(THREADS, 1) void gemm_kernel(
    const float* __restrict__ scales, const float* __restrict__ bias,
    float* __restrict__ out)
{
    extern __shared__ char smem[];
    const uint32_t sb = smem_u32(smem);
    const int tid = threadIdx.x;
    const int wid = tid >> 5;
    const int lane = tid & 31;

    const int tn = blockIdx.x & 15;   // 16 N-tiles (fastest -> A reuse in L2)
    const int tm = blockIdx.x >> 4;   // 64 M-tiles
    const int m0 = tm * BM;
    const int n0 = tn * BN;

    const int warp_m = wid & 1;       // 2 groups of 64 rows
    const int warp_n = wid >> 1;      // 4 groups of 64 cols

    // per-lane ldmatrix addressing (swizzled: unit16 u ^ (row & 7))
    const int a_row = warp_m * 64 + (lane & 15);
    const int a_u0  = lane >> 4;                         // + 2*ks
    const int b_row = warp_n * 64 + (lane & 7) + ((lane >> 4) << 3);
    const int b_u0  = (lane >> 3) & 1;                   // + 2*ks

    float c[4][8][4];
    #pragma unroll
    for (int i = 0; i < 4; i++)
        #pragma unroll
        for (int j = 0; j < 8; j++)
            #pragma unroll
            for (int r = 0; r < 4; r++) c[i][j][r] = 0.0f;

    // prologue: fill STAGES-1 stages
    #pragma unroll
    for (int p = 0; p < STAGES - 1; p++) {
        load_stage(sb + p * STAGE_BYTES, tid, p, m0, n0);
        cp_commit();
    }

    #pragma unroll 1
    for (int kt = 0; kt < KT_ITERS; kt++) {
        cp_wait<STAGES - 2>();
        __syncthreads();

        int pk = kt + STAGES - 1;
        if (pk < KT_ITERS)
            load_stage(sb + (pk % STAGES) * STAGE_BYTES, tid, pk, m0, n0);
        cp_commit();

        const uint32_t sA  = sb + (kt % STAGES) * STAGE_BYTES + OFF_A;
        const uint32_t sBm = sb + (kt % STAGES) * STAGE_BYTES + OFF_B;

        #pragma unroll
        for (int ks = 0; ks < 4; ks++) {
            uint32_t a[4][4], b[4][4];
            #pragma unroll
            for (int i = 0; i < 4; i++) {
                int r = a_row + i * 16;
                uint32_t addr = sA + r * 128 +
                                (((uint32_t)((a_u0 + 2 * ks) ^ (r & 7))) << 4);
                ldsm_x4(a[i], addr);
            }
            #pragma unroll
            for (int j = 0; j < 4; j++) {
                int r = b_row + j * 16;
                uint32_t addr = sBm + r * 128 +
                                (((uint32_t)((b_u0 + 2 * ks) ^ (r & 7))) << 4);
                ldsm_x4(b[j], addr);
            }
            #pragma unroll
            for (int i = 0; i < 4; i++) {
                #pragma unroll
                for (int j = 0; j < 4; j++) {
                    mma16816(c[i][2 * j],     a[i], b[j][0], b[j][1]);
                    mma16816(c[i][2 * j + 1], a[i], b[j][2], b[j][3]);
                }
            }
        }
    }
    cp_wait<0>();

    // ---------------- epilogue: scale * acc + bias ----------------
    const int mrow = lane >> 2;
    const int ncol = (lane & 3) * 2;
    #pragma unroll
    for (int j = 0; j < 8; j++) {
        int n = n0 + warp_n * 64 + j * 8 + ncol;
        float2 s  = *reinterpret_cast<const float2*>(scales + n);
        float2 bb = *reinterpret_cast<const float2*>(bias + n);
        #pragma unroll
        for (int i = 0; i < 4; i++) {
            int m = m0 + warp_m * 64 + i * 16 + mrow;
            float2 v0, v1;
            v0.x = c[i][j][0] * s.x + bb.x;
            v0.y = c[i][j][1] * s.y + bb.y;
            v1.x = c[i][j][2] * s.x + bb.x;
            v1.y = c[i][j][3] * s.y + bb.y;
            *reinterpret_cast<float2*>(out + (size_t)m * NDIM + n) = v0;
            *reinterpret_cast<float2*>(out + (size_t)(m + 8) * NDIM + n) = v1;
        }
    }
}

// ---------------- launch ----------------
extern "C" void kernel_launch(void* const* d_in, const int* in_sizes, int n_in,
                              void* d_out, int out_size) {
    const float* x  = (const float*)d_in[0];
    const int*   wp = (const int*)d_in[1];
    const float* sc = (const float*)d_in[2];
    const float* bi = (const float*)d_in[3];
    float* out = (float*)d_out;

    static bool attr_set = false;
    if (!attr_set) {
        cudaFuncSetAttribute(gemm_kernel,
                             cudaFuncAttributeMaxDynamicSharedMemorySize, SMEM_TOTAL);
        attr_set = true;
    }

    unpack_w_kernel<<<(NDIM * (KDIM / 2)) / 256, 256>>>(wp);            // 32768 blocks
    cvt_x_kernel<<<(MDIM * (KDIM / 4)) / 256, 256>>>((const float4*)x); // 32768 blocks
    gemm_kernel<<<(MDIM / BM) * (NDIM / BN), THREADS, SMEM_TOTAL>>>(sc, bi, out);
}

// round 5
// speedup vs baseline: 3.5852x; 1.0278x over previous
#include <cuda_runtime.h>
#include <cuda_fp16.h>
#include <cstdint>

// ---------------- problem dims ----------------
#define MDIM 8192
#define NDIM 4096
#define KDIM 4096

// ---------------- GEMM tiling ----------------
#define BM 128
#define BN 256
#define BK 64                  // 64 fp16 = 128 B per SMEM row
#define STAGES 4
#define KT_ITERS (KDIM / BK)   // 64
#define THREADS 256            // 8 warps: 2 (m) x 4 (n), warp tile 64x64

// SMEM per stage: A 128*128B = 16KB, B 256*128B = 32KB
#define OFF_A 0
#define OFF_B 16384
#define STAGE_BYTES 49152
#define SMEM_TOTAL (STAGES * STAGE_BYTES)   // 196608

#define PREP_BLOCKS_W (NDIM * (KDIM / 2) / 256)   // 32768
#define PREP_BLOCKS_X (MDIM * (KDIM / 4) / 256)   // 32768

// ---------------- scratch (allocation-free __device__ globals) ----------------
__device__ __half g_A [(size_t)MDIM * KDIM];   // 64 MB fp16 activations
__device__ __half g_Bw[(size_t)NDIM * KDIM];   // 32 MB fp16 unpacked weights

// ---------------- PTX helpers ----------------
__device__ __forceinline__ uint32_t smem_u32(const void* p) {
    return (uint32_t)__cvta_generic_to_shared(p);
}
__device__ __forceinline__ void cp16(uint32_t s, const void* g) {
    asm volatile("cp.async.cg.shared.global [%0], [%1], 16;" :: "r"(s), "l"(g));
}
__device__ __forceinline__ void cp_commit() {
    asm volatile("cp.async.commit_group;" ::: "memory");
}
template <int N>
__device__ __forceinline__ void cp_wait() {
    asm volatile("cp.async.wait_group %0;" :: "n"(N) : "memory");
}
__device__ __forceinline__ void ldsm_x4(uint32_t* d, uint32_t addr) {
    asm volatile("ldmatrix.sync.aligned.m8n8.x4.shared.b16 {%0,%1,%2,%3}, [%4];"
                 : "=r"(d[0]), "=r"(d[1]), "=r"(d[2]), "=r"(d[3]) : "r"(addr));
}
__device__ __forceinline__ void mma16816(float* c, const uint32_t* a,
                                         uint32_t b0, uint32_t b1) {
    asm volatile(
        "mma.sync.aligned.m16n8k16.row.col.f32.f16.f16.f32 "
        "{%0,%1,%2,%3}, {%4,%5,%6,%7}, {%8,%9}, {%0,%1,%2,%3};"
        : "+f"(c[0]), "+f"(c[1]), "+f"(c[2]), "+f"(c[3])
        : "r"(a[0]), "r"(a[1]), "r"(a[2]), "r"(a[3]), "r"(b0), "r"(b1));
}

// ---------------- merged prep: unpack weights + convert activations ----------------
// blocks [0, PREP_BLOCKS_W): int4 -> exact fp16 (XOR 0x88 + sext == nibble-8)
// blocks [PREP_BLOCKS_W, +PREP_BLOCKS_X): x f32 -> fp16
__global__ __launch_bounds__(256) void prep_kernel(const int* __restrict__ wp,
                                                   const float4* __restrict__ x4) {
    int bid = blockIdx.x;
    if (bid < PREP_BLOCKS_W) {
        int idx = bid * 256 + threadIdx.x;        // 0 .. N*K/2-1
        int v = wp[idx];
        float lo = (float)((v & 0xF) - 8);
        float hi = (float)(((v >> 4) & 0xF) - 8);
        reinterpret_cast<__half2*>(g_Bw)[idx] = __floats2half2_rn(lo, hi);
    } else {
        int idx = (bid - PREP_BLOCKS_W) * 256 + threadIdx.x;   // 0 .. M*K/4-1
        float4 v = x4[idx];
        __half2 h0 = __floats2half2_rn(v.x, v.y);
        __half2 h1 = __floats2half2_rn(v.z, v.w);
        __half2* H = reinterpret_cast<__half2*>(g_A);
        H[2 * idx]     = h0;
        H[2 * idx + 1] = h1;
    }
}

// ---------------- stage loader: A 1024 + B 2048 chunks of 16B ----------------
__device__ __forceinline__ void load_stage(uint32_t sbase, int tid, int kt,
                                           int m0, int n0) {
    const char* ga = (const char*)(g_A  + (size_t)m0 * KDIM + kt * BK);
    const char* gb = (const char*)(g_Bw + (size_t)n0 * KDIM + kt * BK);
    #pragma unroll
    for (int j = 0; j < 4; j++) {          // A: 128 rows x 8 units
        int c = tid + j * THREADS;
        int row = c >> 3, u = c & 7;
        uint32_t sa = sbase + OFF_A + row * 128 + (((uint32_t)(u ^ (row & 7))) << 4);
        cp16(sa, ga + (size_t)row * (KDIM * 2) + u * 16);
    }
    #pragma unroll
    for (int j = 0; j < 8; j++) {          // B: 256 rows x 8 units
        int c = tid + j * THREADS;
        int row = c >> 3, u = c & 7;
        uint32_t sa = sbase + OFF_B + row * 128 + (((uint32_t)(u ^ (row & 7))) << 4);
        cp16(sa, gb + (size_t)row * (KDIM * 2) + u * 16);
    }
}

// ---------------- kernel: fp16 mma.sync GEMM + fused epilogue ----------------
__global__ __launch_bounds__(THREADS, 1) void gemm_kernel(
    const float* __restrict__ scales, const float* __restrict__ bias,
    float* __restrict__ out)
{
    extern __shared__ char smem[];
    const uint32_t sb = smem_u32(smem);
    const int tid = threadIdx.x;
    const int wid = tid >> 5;
    const int lane = tid & 31;

    const int tn = blockIdx.x & 15;   // 16 N-tiles (fastest -> A reuse in L2)
    const int tm = blockIdx.x >> 4;   // 64 M-tiles
    const int m0 = tm * BM;
    const int n0 = tn * BN;

    const int warp_m = wid & 1;       // 2 groups of 64 rows
    const int warp_n = wid >> 1;      // 4 groups of 64 cols

    // per-lane ldmatrix addressing (swizzled: unit16 u ^ (row & 7))
    const int a_row = warp_m * 64 + (lane & 15);
    const int a_u0  = lane >> 4;                         // + 2*ks
    const int b_row = warp_n * 64 + (lane & 7) + ((lane >> 4) << 3);
    const int b_u0  = (lane >> 3) & 1;                   // + 2*ks

    float c[4][8][4];
    #pragma unroll
    for (int i = 0; i < 4; i++)
        #pragma unroll
        for (int j = 0; j < 8; j++)
            #pragma unroll
            for (int r = 0; r < 4; r++) c[i][j][r] = 0.0f;

    // prologue: fill STAGES-1 stages
    #pragma unroll
    for (int p = 0; p < STAGES - 1; p++) {
        load_stage(sb + p * STAGE_BYTES, tid, p, m0, n0);
        cp_commit();
    }

    uint32_t af[2][4][4], bf[2][4][4];

    #pragma unroll 1
    for (int kt = 0; kt < KT_ITERS; kt++) {
        cp_wait<STAGES - 2>();
        __syncthreads();

        const uint32_t sA  = sb + (kt % STAGES) * STAGE_BYTES + OFF_A;
        const uint32_t sBm = sb + (kt % STAGES) * STAGE_BYTES + OFF_B;

        // preload ks=0 fragments first so MMAs can start ASAP
        #pragma unroll
        for (int i = 0; i < 4; i++) {
            int r = a_row + i * 16;
            ldsm_x4(af[0][i], sA + r * 128 + (((uint32_t)(a_u0 ^ (r & 7))) << 4));
        }
        #pragma unroll
        for (int j = 0; j < 4; j++) {
            int r = b_row + j * 16;
            ldsm_x4(bf[0][j], sBm + r * 128 + (((uint32_t)(b_u0 ^ (r & 7))) << 4));
        }

        // then queue next stage's global loads
        int pk = kt + STAGES - 1;
        if (pk < KT_ITERS)
            load_stage(sb + (pk % STAGES) * STAGE_BYTES, tid, pk, m0, n0);
        cp_commit();

        #pragma unroll
        for (int ks = 0; ks < 4; ks++) {
            const int cur = ks & 1, nxt = cur ^ 1;
            if (ks < 3) {       // preload ks+1 fragments while MMAs of ks issue
                #pragma unroll
                for (int i = 0; i < 4; i++) {
                    int r = a_row + i * 16;
                    ldsm_x4(af[nxt][i], sA + r * 128 +
                            (((uint32_t)((a_u0 + 2 * (ks + 1)) ^ (r & 7))) << 4));
                }
                #pragma unroll
                for (int j = 0; j < 4; j++) {
                    int r = b_row + j * 16;
                    ldsm_x4(bf[nxt][j], sBm + r * 128 +
                            (((uint32_t)((b_u0 + 2 * (ks + 1)) ^ (r & 7))) << 4));
                }
            }
            #pragma unroll
            for (int i = 0; i < 4; i++) {
                #pragma unroll
                for (int j = 0; j < 4; j++) {
                    mma16816(c[i][2 * j],     af[cur][i], bf[cur][j][0], bf[cur][j][1]);
                    mma16816(c[i][2 * j + 1], af[cur][i], bf[cur][j][2], bf[cur][j][3]);
                }
            }
        }
    }
    cp_wait<0>();

    // ---------------- epilogue: scale * acc + bias ----------------
    const int mrow = lane >> 2;
    const int ncol = (lane & 3) * 2;
    #pragma unroll
    for (int j = 0; j < 8; j++) {
        int n = n0 + warp_n * 64 + j * 8 + ncol;
        float2 s  = *reinterpret_cast<const float2*>(scales + n);
        float2 bb = *reinterpret_cast<const float2*>(bias + n);
        #pragma unroll
        for (int i = 0; i < 4; i++) {
            int m = m0 + warp_m * 64 + i * 16 + mrow;
            float2 v0, v1;
            v0.x = c[i][j][0] * s.x + bb.x;
            v0.y = c[i][j][1] * s.y + bb.y;
            v1.x = c[i][j][2] * s.x + bb.x;
            v1.y = c[i][j][3] * s.y + bb.y;
            *reinterpret_cast<float2*>(out + (size_t)m * NDIM + n) = v0;
            *reinterpret_cast<float2*>(out + (size_t)(m + 8) * NDIM + n) = v1;
        }
    }
}

// ---------------- launch ----------------
extern "C" void kernel_launch(void* const* d_in, const int* in_sizes, int n_in,
                              void* d_out, int out_size) {
    const float* x  = (const float*)d_in[0];
    const int*   wp = (const int*)d_in[1];
    const float* sc = (const float*)d_in[2];
    const float* bi = (const float*)d_in[3];
    float* out = (float*)d_out;

    static bool attr_set = false;
    if (!attr_set) {
        cudaFuncSetAttribute(gemm_kernel,
                             cudaFuncAttributeMaxDynamicSharedMemorySize, SMEM_TOTAL);
        attr_set = true;
    }

    prep_kernel<<<PREP_BLOCKS_W + PREP_BLOCKS_X, 256>>>(wp, (const float4*)x);
    gemm_kernel<<<(MDIM / BM) * (NDIM / BN), THREADS, SMEM_TOTAL>>>(sc, bi, out);
}

// round 6
// speedup vs baseline: 3.6183x; 1.0092x over previous
#include <cuda_runtime.h>
#include <cuda_fp16.h>
#include <cstdint>

// ---------------- problem dims ----------------
#define MDIM 8192
#define NDIM 4096
#define KDIM 4096

// ---------------- GEMM tiling ----------------
#define BM 128
#define BN 128
#define BK 64                  // 64 fp16 = 128 B per SMEM row
#define STAGES 3
#define KT_ITERS (KDIM / BK)   // 64
#define THREADS 256            // 8 warps: 2 (m) x 4 (n), warp tile 64x32
                               // 2 CTAs/SM -> 128 regs/thread cap

// SMEM per stage: A 128*128B = 16KB, B 128*128B = 16KB
#define OFF_A 0
#define OFF_B 16384
#define STAGE_BYTES 32768
#define SMEM_TOTAL (STAGES * STAGE_BYTES)   // 98304 -> 2 CTAs/SM

#define PREP_BLOCKS_W (NDIM * (KDIM / 2) / 256)   // 32768
#define PREP_BLOCKS_X (MDIM * (KDIM / 4) / 256)   // 32768

// ---------------- scratch (allocation-free __device__ globals) ----------------
__device__ __half g_A [(size_t)MDIM * KDIM];   // 64 MB fp16 activations
__device__ __half g_Bw[(size_t)NDIM * KDIM];   // 32 MB fp16 unpacked weights

// ---------------- PTX helpers ----------------
__device__ __forceinline__ uint32_t smem_u32(const void* p) {
    return (uint32_t)__cvta_generic_to_shared(p);
}
__device__ __forceinline__ void cp16(uint32_t s, const void* g) {
    asm volatile("cp.async.cg.shared.global [%0], [%1], 16;" :: "r"(s), "l"(g));
}
__device__ __forceinline__ void cp_commit() {
    asm volatile("cp.async.commit_group;" ::: "memory");
}
template <int N>
__device__ __forceinline__ void cp_wait() {
    asm volatile("cp.async.wait_group %0;" :: "n"(N) : "memory");
}
__device__ __forceinline__ void ldsm_x4(uint32_t* d, uint32_t addr) {
    asm volatile("ldmatrix.sync.aligned.m8n8.x4.shared.b16 {%0,%1,%2,%3}, [%4];"
                 : "=r"(d[0]), "=r"(d[1]), "=r"(d[2]), "=r"(d[3]) : "r"(addr));
}
__device__ __forceinline__ void mma16816(float* c, const uint32_t* a,
                                         uint32_t b0, uint32_t b1) {
    asm volatile(
        "mma.sync.aligned.m16n8k16.row.col.f32.f16.f16.f32 "
        "{%0,%1,%2,%3}, {%4,%5,%6,%7}, {%8,%9}, {%0,%1,%2,%3};"
        : "+f"(c[0]), "+f"(c[1]), "+f"(c[2]), "+f"(c[3])
        : "r"(a[0]), "r"(a[1]), "r"(a[2]), "r"(a[3]), "r"(b0), "r"(b1));
}

// ---------------- merged prep: unpack weights + convert activations ----------------
__global__ __launch_bounds__(256) void prep_kernel(const int* __restrict__ wp,
                                                   const float4* __restrict__ x4) {
    int bid = blockIdx.x;
    if (bid < PREP_BLOCKS_W) {
        int idx = bid * 256 + threadIdx.x;        // 0 .. N*K/2-1
        int v = wp[idx];
        float lo = (float)((v & 0xF) - 8);        // XOR 0x88 + sext == nibble-8
        float hi = (float)(((v >> 4) & 0xF) - 8);
        reinterpret_cast<__half2*>(g_Bw)[idx] = __floats2half2_rn(lo, hi);
    } else {
        int idx = (bid - PREP_BLOCKS_W) * 256 + threadIdx.x;   // 0 .. M*K/4-1
        float4 v = x4[idx];
        __half2 h0 = __floats2half2_rn(v.x, v.y);
        __half2 h1 = __floats2half2_rn(v.z, v.w);
        __half2* H = reinterpret_cast<__half2*>(g_A);
        H[2 * idx]     = h0;
        H[2 * idx + 1] = h1;
    }
}

// ---------------- stage loader: A 1024 + B 1024 chunks of 16B ----------------
__device__ __forceinline__ void load_stage(uint32_t sbase, int tid, int kt,
                                           int m0, int n0) {
    const char* ga = (const char*)(g_A  + (size_t)m0 * KDIM + kt * BK);
    const char* gb = (const char*)(g_Bw + (size_t)n0 * KDIM + kt * BK);
    #pragma unroll
    for (int j = 0; j < 4; j++) {          // A: 128 rows x 8 units
        int c = tid + j * THREADS;
        int row = c >> 3, u = c & 7;
        uint32_t sa = sbase + OFF_A + row * 128 + (((uint32_t)(u ^ (row & 7))) << 4);
        cp16(sa, ga + (size_t)row * (KDIM * 2) + u * 16);
    }
    #pragma unroll
    for (int j = 0; j < 4; j++) {          // B: 128 rows x 8 units
        int c = tid + j * THREADS;
        int row = c >> 3, u = c & 7;
        uint32_t sa = sbase + OFF_B + row * 128 + (((uint32_t)(u ^ (row & 7))) << 4);
        cp16(sa, gb + (size_t)row * (KDIM * 2) + u * 16);
    }
}

// ---------------- kernel: fp16 mma.sync GEMM + fused epilogue ----------------
__global__ __launch_bounds__(THREADS, 2) void gemm_kernel(
    const float* __restrict__ scales, const float* __restrict__ bias,
    float* __restrict__ out)
{
    extern __shared__ char smem[];
    const uint32_t sb = smem_u32(smem);
    const int tid = threadIdx.x;
    const int wid = tid >> 5;
    const int lane = tid & 31;

    const int tn = blockIdx.x & 31;   // 32 N-tiles (fastest -> A reuse in L2)
    const int tm = blockIdx.x >> 5;   // 64 M-tiles
    const int m0 = tm * BM;
    const int n0 = tn * BN;

    const int warp_m = wid & 1;       // 2 groups of 64 rows
    const int warp_n = wid >> 1;      // 4 groups of 32 cols

    // per-lane ldmatrix addressing (swizzled: unit16 u ^ (row & 7))
    const int a_row = warp_m * 64 + (lane & 15);
    const int a_u0  = lane >> 4;                         // + 2*ks
    const int b_row = warp_n * 32 + (lane & 7) + ((lane >> 4) << 3);
    const int b_u0  = (lane >> 3) & 1;                   // + 2*ks

    float c[4][4][4];
    #pragma unroll
    for (int i = 0; i < 4; i++)
        #pragma unroll
        for (int j = 0; j < 4; j++)
            #pragma unroll
            for (int r = 0; r < 4; r++) c[i][j][r] = 0.0f;

    // prologue: fill STAGES-1 stages
    #pragma unroll
    for (int p = 0; p < STAGES - 1; p++) {
        load_stage(sb + p * STAGE_BYTES, tid, p, m0, n0);
        cp_commit();
    }

    #pragma unroll 1
    for (int kt = 0; kt < KT_ITERS; kt++) {
        cp_wait<STAGES - 2>();
        __syncthreads();

        int pk = kt + STAGES - 1;
        if (pk < KT_ITERS)
            load_stage(sb + (pk % STAGES) * STAGE_BYTES, tid, pk, m0, n0);
        cp_commit();

        const uint32_t sA  = sb + (kt % STAGES) * STAGE_BYTES + OFF_A;
        const uint32_t sBm = sb + (kt % STAGES) * STAGE_BYTES + OFF_B;

        #pragma unroll
        for (int ks = 0; ks < 4; ks++) {
            uint32_t a[4][4], b[2][4];
            #pragma unroll
            for (int i = 0; i < 4; i++) {
                int r = a_row + i * 16;
                ldsm_x4(a[i], sA + r * 128 +
                        (((uint32_t)((a_u0 + 2 * ks) ^ (r & 7))) << 4));
            }
            #pragma unroll
            for (int j = 0; j < 2; j++) {
                int r = b_row + j * 16;
                ldsm_x4(b[j], sBm + r * 128 +
                        (((uint32_t)((b_u0 + 2 * ks) ^ (r & 7))) << 4));
            }
            #pragma unroll
            for (int i = 0; i < 4; i++) {
                #pragma unroll
                for (int j = 0; j < 2; j++) {
                    mma16816(c[i][2 * j],     a[i], b[j][0], b[j][1]);
                    mma16816(c[i][2 * j + 1], a[i], b[j][2], b[j][3]);
                }
            }
        }
    }
    cp_wait<0>();

    // ---------------- epilogue: scale * acc + bias ----------------
    const int mrow = lane >> 2;
    const int ncol = (lane & 3) * 2;
    #pragma unroll
    for (int j = 0; j < 4; j++) {
        int n = n0 + warp_n * 32 + j * 8 + ncol;
        float2 s  = *reinterpret_cast<const float2*>(scales + n);
        float2 bb = *reinterpret_cast<const float2*>(bias + n);
        #pragma unroll
        for (int i = 0; i < 4; i++) {
            int m = m0 + warp_m * 64 + i * 16 + mrow;
            float2 v0, v1;
            v0.x = c[i][j][0] * s.x + bb.x;
            v0.y = c[i][j][1] * s.y + bb.y;
            v1.x = c[i][j][2] * s.x + bb.x;
            v1.y = c[i][j][3] * s.y + bb.y;
            *reinterpret_cast<float2*>(out + (size_t)m * NDIM + n) = v0;
            *reinterpret_cast<float2*>(out + (size_t)(m + 8) * NDIM + n) = v1;
        }
    }
}

// ---------------- launch ----------------
extern "C" void kernel_launch(void* const* d_in, const int* in_sizes, int n_in,
                              void* d_out, int out_size) {
    const float* x  = (const float*)d_in[0];
    const int*   wp = (const int*)d_in[1];
    const float* sc = (const float*)d_in[2];
    const float* bi = (const float*)d_in[3];
    float* out = (float*)d_out;

    static bool attr_set = false;
    if (!attr_set) {
        cudaFuncSetAttribute(gemm_kernel,
                             cudaFuncAttributeMaxDynamicSharedMemorySize, SMEM_TOTAL);
        attr_set = true;
    }

    prep_kernel<<<PREP_BLOCKS_W + PREP_BLOCKS_X, 256>>>(wp, (const float4*)x);
    gemm_kernel<<<(MDIM / BM) * (NDIM / BN), THREADS, SMEM_TOTAL>>>(sc, bi, out);
}